// round 1
// baseline (speedup 1.0000x reference)
#include <cuda_runtime.h>
#include <cstddef>

typedef unsigned long long ull;

// ---------------- problem constants (shapes fixed by the dataset) -----------
#define MAXN 100000
#define MAXE 1600000
#define FN   128     // node feature dim (layer1 input)
#define FE   32      // edge feature dim
#define HID  64

// ---------------- device scratch (static: no allocation allowed) ------------
__device__ float g_loop[MAXN * FE];        // self-loop edge attr (mean of incoming)
__device__ float g_cnt [MAXN];             // in-degree counts
__device__ float g_xl  [MAXN * HID];       // source-side transform
__device__ float g_xr  [MAXN * HID];       // target-side transform
__device__ float g_ex  [MAXE + MAXN];      // per-edge exp(logit)
__device__ float g_den [MAXN];             // softmax denominator (-> reciprocal)
__device__ float g_out [MAXN * HID];       // aggregation accumulator / layer output

// ---------------- small helpers ---------------------------------------------
__device__ __forceinline__ ull pk2(float x, float y) {
    ull r; asm("mov.b64 %0, {%1,%2};" : "=l"(r) : "f"(x), "f"(y)); return r;
}
__device__ __forceinline__ void upk2(ull v, float& x, float& y) {
    asm("mov.b64 {%0,%1}, %2;" : "=f"(x), "=f"(y) : "l"(v));
}
__device__ __forceinline__ void ffma2(ull& d, ull a, ull b) {
    asm("fma.rn.f32x2 %0, %1, %2, %0;" : "+l"(d) : "l"(a), "l"(b));
}
__device__ __forceinline__ void redv2(float* p, float x, float y) {
    asm volatile("red.global.add.v2.f32 [%0], {%1,%2};" :: "l"(p), "f"(x), "f"(y) : "memory");
}
__device__ __forceinline__ void redv4(float* p, float4 u) {
    asm volatile("red.global.add.v4.f32 [%0], {%1,%2,%3,%4};"
                 :: "l"(p), "f"(u.x), "f"(u.y), "f"(u.z), "f"(u.w) : "memory");
}

// ---------------- kernel: zero scratch --------------------------------------
__global__ void zero_kernel(int N) {
    const float4 z = make_float4(0.f, 0.f, 0.f, 0.f);
    float4* o4 = reinterpret_cast<float4*>(g_out);
    float4* l4 = reinterpret_cast<float4*>(g_loop);
    float4* c4 = reinterpret_cast<float4*>(g_cnt);
    float4* d4 = reinterpret_cast<float4*>(g_den);
    int total = N * 16;                      // g_out as float4 is largest
    int stride = gridDim.x * blockDim.x;
    for (int k = blockIdx.x * blockDim.x + threadIdx.x; k < total; k += stride) {
        o4[k] = z;
        if (k < N * 8) l4[k] = z;
        if (k < N / 4) { c4[k] = z; d4[k] = z; }
    }
}

// ---------------- kernel: self-loop attr accumulation ------------------------
__global__ void pre_kernel(const int* __restrict__ ei, const float* __restrict__ ea, int E) {
    int stride = gridDim.x * blockDim.x;
    for (int i = blockIdx.x * blockDim.x + threadIdx.x; i < E; i += stride) {
        int d = ei[E + i];
        atomicAdd(&g_cnt[d], 1.f);
        const float4* ea4 = reinterpret_cast<const float4*>(ea) + (size_t)i * 8;
        float* base = g_loop + (size_t)d * FE;
        #pragma unroll
        for (int q = 0; q < 8; ++q) redv4(base + 4 * q, ea4[q]);
    }
}

__global__ void div_kernel(int N) {
    float4* l4 = reinterpret_cast<float4*>(g_loop);
    int total = N * 8;
    int stride = gridDim.x * blockDim.x;
    for (int t = blockIdx.x * blockDim.x + threadIdx.x; t < total; t += stride) {
        int n = t >> 3;
        float inv = 1.f / fmaxf(g_cnt[n], 1.f);
        float4 v = l4[t];
        v.x *= inv; v.y *= inv; v.z *= inv; v.w *= inv;
        l4[t] = v;
    }
}

// ---------------- kernel: node linear transforms (xl | xr) -------------------
// Block: 256 threads, 64 nodes. Each thread: 2 nodes x 8 output PAIRS (16 outs).
// W chunk of 16 input rows staged per round; x rows staged once.
template<int IN, bool FROM_OUT>
__global__ void lin_kernel(const float* __restrict__ inp,
                           const float* __restrict__ Wl, const float* __restrict__ bl,
                           const float* __restrict__ Wr, const float* __restrict__ br,
                           const float* __restrict__ prevBias, int N) {
    constexpr int NB = 64;
    __shared__ __align__(16) float xs[NB * (IN + 1)];
    __shared__ __align__(16) float ws[16 * 128];
    const int nb = blockIdx.x * NB;
    const int t = threadIdx.x;

    // stage inputs (apply bias+relu of previous layer when FROM_OUT)
    for (int idx = t; idx < NB * IN; idx += 256) {
        int n = idx / IN, j = idx - n * IN;
        int g = nb + n;
        float v = 0.f;
        if (g < N) {
            if (FROM_OUT) v = fmaxf(g_out[(size_t)g * HID + j] + prevBias[j], 0.f);
            else          v = inp[(size_t)g * IN + j];
        }
        xs[n * (IN + 1) + j] = v;
    }
    __syncthreads();
    if (FROM_OUT) {
        // g_out rows for this block fully consumed -> zero for next layer; also den
        for (int idx = t; idx < NB * HID; idx += 256) {
            int n = idx / HID; int g = nb + n;
            if (g < N) g_out[(size_t)g * HID + (idx - n * HID)] = 0.f;
        }
        if (t < NB && nb + t < N) g_den[nb + t] = 0.f;
    }

    const int pg = t & 7;
    const int n0 = (t >> 3) * 2, n1 = n0 + 1;
    ull acc0[8], acc1[8];
    #pragma unroll
    for (int q = 0; q < 8; ++q) { acc0[q] = 0ull; acc1[q] = 0ull; }
    const ull* wsu = reinterpret_cast<const ull*>(ws);

    for (int c = 0; c < IN / 16; ++c) {
        __syncthreads();
        for (int idx = t; idx < 16 * 128; idx += 256) {
            int j = idx >> 7, o = idx & 127;
            int row = c * 16 + j;
            ws[idx] = (o < HID) ? Wl[row * HID + o] : Wr[row * HID + (o - HID)];
        }
        __syncthreads();
        #pragma unroll
        for (int j = 0; j < 16; ++j) {
            float a0 = xs[n0 * (IN + 1) + c * 16 + j];
            float a1 = xs[n1 * (IN + 1) + c * 16 + j];
            ull p0 = pk2(a0, a0), p1 = pk2(a1, a1);
            #pragma unroll
            for (int q = 0; q < 8; ++q) {
                ull wv = wsu[j * 64 + pg + 8 * q];
                ffma2(acc0[q], p0, wv);
                ffma2(acc1[q], p1, wv);
            }
        }
    }

    float2* xl2 = reinterpret_cast<float2*>(g_xl);
    float2* xr2 = reinterpret_cast<float2*>(g_xr);
    #pragma unroll
    for (int which = 0; which < 2; ++which) {
        int n = which ? n1 : n0;
        int g = nb + n;
        if (g >= N) continue;
        ull* acc = which ? acc1 : acc0;
        #pragma unroll
        for (int q = 0; q < 8; ++q) {
            int p = pg + 8 * q;
            int o = 2 * p;
            float vx, vy; upk2(acc[q], vx, vy);
            if (o < HID) {
                xl2[(size_t)g * 32 + p] = make_float2(vx + bl[o], vy + bl[o + 1]);
            } else {
                xr2[(size_t)g * 32 + (p - 32)] = make_float2(vx + br[o - HID], vy + br[o - HID + 1]);
            }
        }
    }
}

// ---------------- kernel: edge pass A (logit -> exp, den) --------------------
// warp per edge; lane owns output dims (2*lane, 2*lane+1); We in registers.
__global__ void edgeA_kernel(const int* __restrict__ ei, const float* __restrict__ ea,
                             const float* __restrict__ We, const float* __restrict__ att,
                             int E, int N) {
    __shared__ ull sEA[8][32];
    const int lane = threadIdx.x & 31;
    const int w = threadIdx.x >> 5;
    const int gw = blockIdx.x * 8 + w;
    const int gws = gridDim.x * 8;
    const int Etot = E + N;

    // preload We column pair + att pair
    ull wreg[32];
    const float2* We2 = reinterpret_cast<const float2*>(We);
    #pragma unroll
    for (int j = 0; j < 32; ++j) {
        float2 wv = We2[j * 32 + lane];
        wreg[j] = pk2(wv.x, wv.y);
    }
    const float2 av = reinterpret_cast<const float2*>(att)[lane];
    const float2* xl2 = reinterpret_cast<const float2*>(g_xl);
    const float2* xr2 = reinterpret_cast<const float2*>(g_xr);

    for (int i = gw; i < Etot; i += gws) {
        int s, d; const float* eaP;
        if (i < E) { s = ei[i]; d = ei[E + i]; eaP = ea + (size_t)i * FE; }
        else       { s = i - E; d = s;        eaP = g_loop + (size_t)s * FE; }

        float ev = eaP[lane];
        sEA[w][lane] = pk2(ev, ev);
        __syncwarp();

        float2 xa = xl2[(size_t)s * 32 + lane];
        float2 xb = xr2[(size_t)d * 32 + lane];
        ull acc0 = pk2(xa.x + xb.x, xa.y + xb.y);
        ull acc1 = 0ull;
        #pragma unroll
        for (int j = 0; j < 32; j += 2) {
            ffma2(acc0, sEA[w][j],     wreg[j]);
            ffma2(acc1, sEA[w][j + 1], wreg[j + 1]);
        }
        float m0, m1, e0, e1;
        upk2(acc0, m0, m1); upk2(acc1, e0, e1);
        m0 += e0; m1 += e1;
        m0 = (m0 > 0.f) ? m0 : 0.2f * m0;        // leaky relu
        m1 = (m1 > 0.f) ? m1 : 0.2f * m1;
        float p = m0 * av.x + m1 * av.y;
        #pragma unroll
        for (int off = 16; off > 0; off >>= 1)
            p += __shfl_xor_sync(0xffffffffu, p, off);
        if (lane == 0) {
            float exv = __expf(p);
            g_ex[i] = exv;
            atomicAdd(&g_den[d], exv);
        }
        __syncwarp();
    }
}

__global__ void rcp_kernel(int N) {
    int t = blockIdx.x * blockDim.x + threadIdx.x;
    if (t < N) g_den[t] = 1.f / g_den[t];
}

// ---------------- kernel: edge pass B (weighted scatter) ---------------------
__global__ void edgeB_kernel(const int* __restrict__ ei, int E, int N) {
    const int lane = threadIdx.x & 31;
    const int gw = blockIdx.x * 8 + (threadIdx.x >> 5);
    const int gws = gridDim.x * 8;
    const int Etot = E + N;
    const float2* xl2 = reinterpret_cast<const float2*>(g_xl);

    for (int i = gw; i < Etot; i += gws) {
        int s, d;
        if (i < E) { s = ei[i]; d = ei[E + i]; }
        else       { s = i - E; d = s; }
        float a = g_ex[i] * g_den[d];            // g_den holds reciprocal
        float2 xv = xl2[(size_t)s * 32 + lane];
        redv2(g_out + (size_t)d * HID + 2 * lane, xv.x * a, xv.y * a);
    }
}

// ---------------- kernel: final MLP at node_idx ------------------------------
__global__ void fin_kernel(const int* __restrict__ idx, const float* __restrict__ bias2,
                           const float* __restrict__ y,
                           const float* __restrict__ W0, const float* __restrict__ b0,
                           const float* __restrict__ W1, const float* __restrict__ b1,
                           const float* __restrict__ W2, const float* __restrict__ b2,
                           float* __restrict__ dout, int M, int rf) {
    __shared__ float sh[4][64];
    __shared__ float sz[4][32];
    const int w = threadIdx.x >> 5, lane = threadIdx.x & 31;
    const int m = blockIdx.x * 4 + w;
    if (m >= M) return;
    const int v = idx[m];

    float h0 = fmaxf(g_out[(size_t)v * HID + lane]      + bias2[lane],      0.f);
    float h1 = fmaxf(g_out[(size_t)v * HID + 32 + lane] + bias2[32 + lane], 0.f);
    sh[w][lane] = h0; sh[w][32 + lane] = h1;
    __syncwarp();

    int k = v / rf;
    float y0 = y[2 * k], y1 = y[2 * k + 1];
    float q0 = fmaxf(y0 * W0[0] + y1 * W0[2] + b0[0], 0.f);
    float q1 = fmaxf(y0 * W0[1] + y1 * W0[3] + b0[1], 0.f);

    float z = b1[lane];
    #pragma unroll
    for (int j = 0; j < 64; ++j) z += sh[w][j] * W1[j * 32 + lane];
    z += q0 * W1[64 * 32 + lane] + q1 * W1[65 * 32 + lane];
    z = fmaxf(z, 0.f);
    sz[w][lane] = z;
    __syncwarp();

    float o = b2[lane];
    #pragma unroll
    for (int j = 0; j < 32; ++j) o += sz[w][j] * W2[j * 32 + lane];
    dout[m * 32 + lane] = o;
}

// ---------------- launch ------------------------------------------------------
extern "C" void kernel_launch(void* const* d_in, const int* in_sizes, int n_in,
                              void* d_out, int out_size) {
    const float* x    = (const float*)d_in[0];
    const float* ea   = (const float*)d_in[1];
    const float* y    = (const float*)d_in[2];
    const float* Wl1  = (const float*)d_in[3];
    const float* bl1  = (const float*)d_in[4];
    const float* Wr1  = (const float*)d_in[5];
    const float* br1  = (const float*)d_in[6];
    const float* We1  = (const float*)d_in[7];
    const float* att1 = (const float*)d_in[8];
    const float* bias1= (const float*)d_in[9];
    const float* Wl2  = (const float*)d_in[10];
    const float* bl2  = (const float*)d_in[11];
    const float* Wr2  = (const float*)d_in[12];
    const float* br2  = (const float*)d_in[13];
    const float* We2  = (const float*)d_in[14];
    const float* att2 = (const float*)d_in[15];
    const float* bias2= (const float*)d_in[16];
    const float* W0   = (const float*)d_in[17];
    const float* b0   = (const float*)d_in[18];
    const float* W1   = (const float*)d_in[19];
    const float* b1   = (const float*)d_in[20];
    const float* W2   = (const float*)d_in[21];
    const float* b2   = (const float*)d_in[22];
    const int*   ei   = (const int*)  d_in[23];
    const int*   nidx = (const int*)  d_in[24];

    const int N  = in_sizes[0] / FN;
    const int E  = in_sizes[23] / 2;
    const int M  = in_sizes[24];
    const int NG = in_sizes[2] / 2;
    const int rf = N / NG;

    const int EB = 4096;   // edge-kernel grid (grid-stride, warp per edge)

    zero_kernel<<<4096, 256>>>(N);
    pre_kernel <<<4096, 256>>>(ei, ea, E);
    div_kernel <<<(N * 8 + 255) / 256, 256>>>(N);

    // ---- layer 1 ----
    lin_kernel<FN, false><<<(N + 63) / 64, 256>>>(x, Wl1, bl1, Wr1, br1, nullptr, N);
    edgeA_kernel<<<EB, 256>>>(ei, ea, We1, att1, E, N);
    rcp_kernel  <<<(N + 255) / 256, 256>>>(N);
    edgeB_kernel<<<EB, 256>>>(ei, E, N);

    // ---- layer 2 (lin reads g_out, applies bias1+relu, zeroes g_out/g_den) ----
    lin_kernel<HID, true><<<(N + 63) / 64, 256>>>(x, Wl2, bl2, Wr2, br2, bias1, N);
    edgeA_kernel<<<EB, 256>>>(ei, ea, We2, att2, E, N);
    rcp_kernel  <<<(N + 255) / 256, 256>>>(N);
    edgeB_kernel<<<EB, 256>>>(ei, E, N);

    // ---- final MLP at node_idx ----
    fin_kernel<<<(M + 3) / 4, 128>>>(nidx, bias2, y, W0, b0, W1, b1, W2, b2,
                                     (float*)d_out, M, rf);
}

// round 2
// speedup vs baseline: 1.9650x; 1.9650x over previous
#include <cuda_runtime.h>
#include <cstddef>

typedef unsigned long long ull;
typedef unsigned int uint;

// ---------------- problem constants (shapes fixed by the dataset) -----------
#define MAXN 100000
#define MAXE 1600000
#define FN   128     // node feature dim (layer1 input)
#define FE   32      // edge feature dim
#define HID  64

// ---------------- device scratch (static: no allocation allowed) ------------
__device__ float g_loop[MAXN * FE];        // self-loop edge attr (mean of incoming)
__device__ float g_cnt [MAXN];             // in-degree counts
__device__ float g_xl  [MAXN * HID];       // source-side transform
__device__ float g_xr  [MAXN * HID];       // target-side transform
__device__ float g_ex  [MAXE + MAXN];      // per-edge exp(logit)
__device__ float g_den [MAXN];             // softmax denominator (-> reciprocal)
__device__ float g_out [MAXN * HID];       // aggregation accumulator / layer output

// ---------------- small helpers ---------------------------------------------
__device__ __forceinline__ ull pk2(float x, float y) {
    ull r; asm("mov.b64 %0, {%1,%2};" : "=l"(r) : "f"(x), "f"(y)); return r;
}
__device__ __forceinline__ void upk2(ull v, float& x, float& y) {
    asm("mov.b64 {%0,%1}, %2;" : "=f"(x), "=f"(y) : "l"(v));
}
__device__ __forceinline__ void ffma2(ull& d, ull a, ull b) {
    asm("fma.rn.f32x2 %0, %1, %2, %0;" : "+l"(d) : "l"(a), "l"(b));
}
__device__ __forceinline__ void redv2(float* p, float x, float y) {
    asm volatile("red.global.add.v2.f32 [%0], {%1,%2};" :: "l"(p), "f"(x), "f"(y) : "memory");
}
__device__ __forceinline__ void redv4(float* p, float4 u) {
    asm volatile("red.global.add.v4.f32 [%0], {%1,%2,%3,%4};"
                 :: "l"(p), "f"(u.x), "f"(u.y), "f"(u.z), "f"(u.w) : "memory");
}
__device__ __forceinline__ uint to_tf32(float f) {
    uint r; asm("cvt.rna.tf32.f32 %0, %1;" : "=r"(r) : "f"(f)); return r;
}
__device__ __forceinline__ void mma_tf32(float acc[4], const uint a[4], uint b0, uint b1) {
    asm volatile(
        "mma.sync.aligned.m16n8k8.row.col.f32.tf32.tf32.f32 "
        "{%0,%1,%2,%3}, {%4,%5,%6,%7}, {%8,%9}, {%0,%1,%2,%3};"
        : "+f"(acc[0]), "+f"(acc[1]), "+f"(acc[2]), "+f"(acc[3])
        : "r"(a[0]), "r"(a[1]), "r"(a[2]), "r"(a[3]), "r"(b0), "r"(b1));
}

// ---------------- kernel: zero scratch --------------------------------------
__global__ void zero_kernel(int N) {
    const float4 z = make_float4(0.f, 0.f, 0.f, 0.f);
    float4* o4 = reinterpret_cast<float4*>(g_out);
    float4* l4 = reinterpret_cast<float4*>(g_loop);
    float4* c4 = reinterpret_cast<float4*>(g_cnt);
    float4* d4 = reinterpret_cast<float4*>(g_den);
    int total = N * 16;                      // g_out as float4 is largest
    int stride = gridDim.x * blockDim.x;
    for (int k = blockIdx.x * blockDim.x + threadIdx.x; k < total; k += stride) {
        o4[k] = z;
        if (k < N * 8) l4[k] = z;
        if (k < N / 4) { c4[k] = z; d4[k] = z; }
    }
}

// ---------------- kernel: self-loop attr accumulation ------------------------
__global__ void pre_kernel(const int* __restrict__ ei, const float* __restrict__ ea, int E) {
    int stride = gridDim.x * blockDim.x;
    for (int i = blockIdx.x * blockDim.x + threadIdx.x; i < E; i += stride) {
        int d = ei[E + i];
        atomicAdd(&g_cnt[d], 1.f);
        const float4* ea4 = reinterpret_cast<const float4*>(ea) + (size_t)i * 8;
        float* base = g_loop + (size_t)d * FE;
        #pragma unroll
        for (int q = 0; q < 8; ++q) redv4(base + 4 * q, ea4[q]);
    }
}

__global__ void div_kernel(int N) {
    float4* l4 = reinterpret_cast<float4*>(g_loop);
    int total = N * 8;
    int stride = gridDim.x * blockDim.x;
    for (int t = blockIdx.x * blockDim.x + threadIdx.x; t < total; t += stride) {
        int n = t >> 3;
        float inv = 1.f / fmaxf(g_cnt[n], 1.f);
        float4 v = l4[t];
        v.x *= inv; v.y *= inv; v.z *= inv; v.w *= inv;
        l4[t] = v;
    }
}

// ---------------- kernel: node linear transforms (xl | xr) -------------------
template<int IN, bool FROM_OUT>
__global__ void lin_kernel(const float* __restrict__ inp,
                           const float* __restrict__ Wl, const float* __restrict__ bl,
                           const float* __restrict__ Wr, const float* __restrict__ br,
                           const float* __restrict__ prevBias, int N) {
    constexpr int NB = 64;
    __shared__ __align__(16) float xs[NB * (IN + 1)];
    __shared__ __align__(16) float ws[16 * 128];
    const int nb = blockIdx.x * NB;
    const int t = threadIdx.x;

    for (int idx = t; idx < NB * IN; idx += 256) {
        int n = idx / IN, j = idx - n * IN;
        int g = nb + n;
        float v = 0.f;
        if (g < N) {
            if (FROM_OUT) v = fmaxf(g_out[(size_t)g * HID + j] + prevBias[j], 0.f);
            else          v = inp[(size_t)g * IN + j];
        }
        xs[n * (IN + 1) + j] = v;
    }
    __syncthreads();
    if (FROM_OUT) {
        for (int idx = t; idx < NB * HID; idx += 256) {
            int n = idx / HID; int g = nb + n;
            if (g < N) g_out[(size_t)g * HID + (idx - n * HID)] = 0.f;
        }
        if (t < NB && nb + t < N) g_den[nb + t] = 0.f;
    }

    const int pg = t & 7;
    const int n0 = (t >> 3) * 2, n1 = n0 + 1;
    ull acc0[8], acc1[8];
    #pragma unroll
    for (int q = 0; q < 8; ++q) { acc0[q] = 0ull; acc1[q] = 0ull; }
    const ull* wsu = reinterpret_cast<const ull*>(ws);

    for (int c = 0; c < IN / 16; ++c) {
        __syncthreads();
        for (int idx = t; idx < 16 * 128; idx += 256) {
            int j = idx >> 7, o = idx & 127;
            int row = c * 16 + j;
            ws[idx] = (o < HID) ? Wl[row * HID + o] : Wr[row * HID + (o - HID)];
        }
        __syncthreads();
        #pragma unroll
        for (int j = 0; j < 16; ++j) {
            float a0 = xs[n0 * (IN + 1) + c * 16 + j];
            float a1 = xs[n1 * (IN + 1) + c * 16 + j];
            ull p0 = pk2(a0, a0), p1 = pk2(a1, a1);
            #pragma unroll
            for (int q = 0; q < 8; ++q) {
                ull wv = wsu[j * 64 + pg + 8 * q];
                ffma2(acc0[q], p0, wv);
                ffma2(acc1[q], p1, wv);
            }
        }
    }

    float2* xl2 = reinterpret_cast<float2*>(g_xl);
    float2* xr2 = reinterpret_cast<float2*>(g_xr);
    #pragma unroll
    for (int which = 0; which < 2; ++which) {
        int n = which ? n1 : n0;
        int g = nb + n;
        if (g >= N) continue;
        ull* acc = which ? acc1 : acc0;
        #pragma unroll
        for (int q = 0; q < 8; ++q) {
            int p = pg + 8 * q;
            int o = 2 * p;
            float vx, vy; upk2(acc[q], vx, vy);
            if (o < HID) {
                xl2[(size_t)g * 32 + p] = make_float2(vx + bl[o], vy + bl[o + 1]);
            } else {
                xr2[(size_t)g * 32 + (p - 32)] = make_float2(vx + br[o - HID], vy + br[o - HID + 1]);
            }
        }
    }
}

// ---------------- kernel: edge pass A — tensor-core e-GEMM + logits ----------
// Warp handles a tile of 16 edges x HID(64). e = ea(16x32) @ We(32x64) via
// 8 n-tiles x 4 k-steps of mma.m16n8k8.tf32. Epilogue in fp32.
__global__ __launch_bounds__(256) void edgeA_kernel(
        const int* __restrict__ ei, const float* __restrict__ ea,
        const float* __restrict__ We, const float* __restrict__ att,
        int E, int N) {
    __shared__ uint Wes[32 * 68];            // tf32-converted We, padded rows

    const int t = threadIdx.x;
    // stage We (32x64) -> smem as tf32
    for (int idx = t; idx < 32 * 64; idx += 256) {
        int row = idx >> 6, col = idx & 63;
        Wes[row * 68 + col] = to_tf32(We[idx]);
    }
    __syncthreads();

    const int lane = t & 31;
    const int w = t >> 5;
    const int g = lane >> 2;                 // row group 0..7
    const int c = lane & 3;                  // col-in-group 0..3
    const int Etot = E + N;
    const int nTiles = (Etot + 15) >> 4;
    const int gw = blockIdx.x * 8 + w;
    const int gws = gridDim.x * 8;

    const float2* xl2 = reinterpret_cast<const float2*>(g_xl);
    const float2* xr2 = reinterpret_cast<const float2*>(g_xr);
    const float2* att2 = reinterpret_cast<const float2*>(att);

    for (int tile = gw; tile < nTiles; tile += gws) {
        const int i0 = tile << 4;
        const int rowA = i0 + g;             // this lane's two edge rows
        const int rowB = i0 + g + 8;

        int sA, dA, sB, dB;
        const float *pA, *pB;
        if (rowA < E)         { sA = ei[rowA]; dA = ei[E + rowA]; pA = ea + (size_t)rowA * FE; }
        else if (rowA < Etot) { sA = dA = rowA - E; pA = g_loop + (size_t)sA * FE; }
        else                  { sA = dA = 0; pA = ea; }
        if (rowB < E)         { sB = ei[rowB]; dB = ei[E + rowB]; pB = ea + (size_t)rowB * FE; }
        else if (rowB < Etot) { sB = dB = rowB - E; pB = g_loop + (size_t)sB * FE; }
        else                  { sB = dB = 0; pB = ea; }

        // A fragments for all 4 k-steps (m16k8 each)
        uint afr[4][4];
        #pragma unroll
        for (int ks = 0; ks < 4; ++ks) {
            afr[ks][0] = to_tf32(pA[ks * 8 + c]);
            afr[ks][1] = to_tf32(pB[ks * 8 + c]);
            afr[ks][2] = to_tf32(pA[ks * 8 + c + 4]);
            afr[ks][3] = to_tf32(pB[ks * 8 + c + 4]);
        }

        float partA = 0.f, partB = 0.f;
        #pragma unroll
        for (int nt = 0; nt < 8; ++nt) {
            float acc[4] = {0.f, 0.f, 0.f, 0.f};
            #pragma unroll
            for (int ks = 0; ks < 4; ++ks) {
                uint b0 = Wes[(ks * 8 + c)     * 68 + nt * 8 + g];
                uint b1 = Wes[(ks * 8 + c + 4) * 68 + nt * 8 + g];
                mma_tf32(acc, afr[ks], b0, b1);
            }
            // gather xl[s]+xr[d] for the 2x2 accumulator footprint
            float2 xlA = xl2[(size_t)sA * 32 + nt * 4 + c];
            float2 xrA = xr2[(size_t)dA * 32 + nt * 4 + c];
            float2 xlB = xl2[(size_t)sB * 32 + nt * 4 + c];
            float2 xrB = xr2[(size_t)dB * 32 + nt * 4 + c];
            float u0 = acc[0] + xlA.x + xrA.x;
            float u1 = acc[1] + xlA.y + xrA.y;
            float u2 = acc[2] + xlB.x + xrB.x;
            float u3 = acc[3] + xlB.y + xrB.y;
            u0 = fmaxf(u0, 0.f) + 0.2f * fminf(u0, 0.f);
            u1 = fmaxf(u1, 0.f) + 0.2f * fminf(u1, 0.f);
            u2 = fmaxf(u2, 0.f) + 0.2f * fminf(u2, 0.f);
            u3 = fmaxf(u3, 0.f) + 0.2f * fminf(u3, 0.f);
            float2 av = att2[nt * 4 + c];
            partA = fmaf(u0, av.x, fmaf(u1, av.y, partA));
            partB = fmaf(u2, av.x, fmaf(u3, av.y, partB));
        }
        // reduce across the 4 lanes of each row group
        partA += __shfl_xor_sync(0xffffffffu, partA, 1);
        partA += __shfl_xor_sync(0xffffffffu, partA, 2);
        partB += __shfl_xor_sync(0xffffffffu, partB, 1);
        partB += __shfl_xor_sync(0xffffffffu, partB, 2);
        if (c == 0) {
            if (rowA < Etot) {
                float e = __expf(partA);
                g_ex[rowA] = e;
                atomicAdd(&g_den[dA], e);
            }
            if (rowB < Etot) {
                float e = __expf(partB);
                g_ex[rowB] = e;
                atomicAdd(&g_den[dB], e);
            }
        }
    }
}

__global__ void rcp_kernel(int N) {
    int t = blockIdx.x * blockDim.x + threadIdx.x;
    if (t < N) g_den[t] = 1.f / g_den[t];
}

// ---------------- kernel: edge pass B (weighted scatter) ---------------------
__global__ void edgeB_kernel(const int* __restrict__ ei, int E, int N) {
    const int lane = threadIdx.x & 31;
    const int gw = blockIdx.x * 8 + (threadIdx.x >> 5);
    const int gws = gridDim.x * 8;
    const int Etot = E + N;
    const float2* xl2 = reinterpret_cast<const float2*>(g_xl);

    for (int i = gw; i < Etot; i += gws) {
        int s, d;
        if (i < E) { s = ei[i]; d = ei[E + i]; }
        else       { s = i - E; d = s; }
        float a = g_ex[i] * g_den[d];            // g_den holds reciprocal
        float2 xv = xl2[(size_t)s * 32 + lane];
        redv2(g_out + (size_t)d * HID + 2 * lane, xv.x * a, xv.y * a);
    }
}

// ---------------- kernel: final MLP at node_idx ------------------------------
__global__ void fin_kernel(const int* __restrict__ idx, const float* __restrict__ bias2,
                           const float* __restrict__ y,
                           const float* __restrict__ W0, const float* __restrict__ b0,
                           const float* __restrict__ W1, const float* __restrict__ b1,
                           const float* __restrict__ W2, const float* __restrict__ b2,
                           float* __restrict__ dout, int M, int rf) {
    __shared__ float sh[4][64];
    __shared__ float sz[4][32];
    const int w = threadIdx.x >> 5, lane = threadIdx.x & 31;
    const int m = blockIdx.x * 4 + w;
    if (m >= M) return;
    const int v = idx[m];

    float h0 = fmaxf(g_out[(size_t)v * HID + lane]      + bias2[lane],      0.f);
    float h1 = fmaxf(g_out[(size_t)v * HID + 32 + lane] + bias2[32 + lane], 0.f);
    sh[w][lane] = h0; sh[w][32 + lane] = h1;
    __syncwarp();

    int k = v / rf;
    float y0 = y[2 * k], y1 = y[2 * k + 1];
    float q0 = fmaxf(y0 * W0[0] + y1 * W0[2] + b0[0], 0.f);
    float q1 = fmaxf(y0 * W0[1] + y1 * W0[3] + b0[1], 0.f);

    float z = b1[lane];
    #pragma unroll
    for (int j = 0; j < 64; ++j) z += sh[w][j] * W1[j * 32 + lane];
    z += q0 * W1[64 * 32 + lane] + q1 * W1[65 * 32 + lane];
    z = fmaxf(z, 0.f);
    sz[w][lane] = z;
    __syncwarp();

    float o = b2[lane];
    #pragma unroll
    for (int j = 0; j < 32; ++j) o += sz[w][j] * W2[j * 32 + lane];
    dout[m * 32 + lane] = o;
}

// ---------------- launch ------------------------------------------------------
extern "C" void kernel_launch(void* const* d_in, const int* in_sizes, int n_in,
                              void* d_out, int out_size) {
    const float* x    = (const float*)d_in[0];
    const float* ea   = (const float*)d_in[1];
    const float* y    = (const float*)d_in[2];
    const float* Wl1  = (const float*)d_in[3];
    const float* bl1  = (const float*)d_in[4];
    const float* Wr1  = (const float*)d_in[5];
    const float* br1  = (const float*)d_in[6];
    const float* We1  = (const float*)d_in[7];
    const float* att1 = (const float*)d_in[8];
    const float* bias1= (const float*)d_in[9];
    const float* Wl2  = (const float*)d_in[10];
    const float* bl2  = (const float*)d_in[11];
    const float* Wr2  = (const float*)d_in[12];
    const float* br2  = (const float*)d_in[13];
    const float* We2  = (const float*)d_in[14];
    const float* att2 = (const float*)d_in[15];
    const float* bias2= (const float*)d_in[16];
    const float* W0   = (const float*)d_in[17];
    const float* b0   = (const float*)d_in[18];
    const float* W1   = (const float*)d_in[19];
    const float* b1   = (const float*)d_in[20];
    const float* W2   = (const float*)d_in[21];
    const float* b2   = (const float*)d_in[22];
    const int*   ei   = (const int*)  d_in[23];
    const int*   nidx = (const int*)  d_in[24];

    const int N  = in_sizes[0] / FN;
    const int E  = in_sizes[23] / 2;
    const int M  = in_sizes[24];
    const int NG = in_sizes[2] / 2;
    const int rf = N / NG;

    const int EB  = 4096;   // edgeB grid (grid-stride, warp per edge)
    const int EAB = 2048;   // edgeA grid (grid-stride, warp per 16-edge tile)

    zero_kernel<<<4096, 256>>>(N);
    pre_kernel <<<4096, 256>>>(ei, ea, E);
    div_kernel <<<(N * 8 + 255) / 256, 256>>>(N);

    // ---- layer 1 ----
    lin_kernel<FN, false><<<(N + 63) / 64, 256>>>(x, Wl1, bl1, Wr1, br1, nullptr, N);
    edgeA_kernel<<<EAB, 256>>>(ei, ea, We1, att1, E, N);
    rcp_kernel  <<<(N + 255) / 256, 256>>>(N);
    edgeB_kernel<<<EB, 256>>>(ei, E, N);

    // ---- layer 2 (lin reads g_out, applies bias1+relu, zeroes g_out/g_den) ----
    lin_kernel<HID, true><<<(N + 63) / 64, 256>>>(x, Wl2, bl2, Wr2, br2, bias1, N);
    edgeA_kernel<<<EAB, 256>>>(ei, ea, We2, att2, E, N);
    rcp_kernel  <<<(N + 255) / 256, 256>>>(N);
    edgeB_kernel<<<EB, 256>>>(ei, E, N);

    // ---- final MLP at node_idx ----
    fin_kernel<<<(M + 3) / 4, 128>>>(nidx, bias2, y, W0, b0, W1, b1, W2, b2,
                                     (float*)d_out, M, rf);
}

// round 3
// speedup vs baseline: 2.0173x; 1.0266x over previous
#include <cuda_runtime.h>
#include <cstddef>

typedef unsigned long long ull;
typedef unsigned int uint;

// ---------------- problem constants (shapes fixed by the dataset) -----------
#define MAXN 100000
#define MAXE 1600000
#define MAXET (MAXE + MAXN)
#define FN   128     // node feature dim (layer1 input)
#define FE   32      // edge feature dim
#define HID  64

// ---------------- device scratch (static: no allocation allowed) ------------
__device__ float g_loop[MAXN * FE];        // self-loop edge attr (mean of incoming)
__device__ float g_xl  [MAXN * HID];       // source-side transform
__device__ float g_xr  [MAXN * HID];       // target-side transform
__device__ float g_exc [MAXET];            // exp(logit) in CSR slot order
__device__ float g_out [MAXN * HID];       // layer output
__device__ int   g_deg [MAXN];
__device__ int   g_rowptr[MAXN + 1];
__device__ int   g_cur [MAXN];
__device__ int   g_csr_src[MAXET];
__device__ int   g_csr_eid[MAXET];
__device__ int   g_csr_dst[MAXET];

// ---------------- small helpers ---------------------------------------------
__device__ __forceinline__ ull pk2(float x, float y) {
    ull r; asm("mov.b64 %0, {%1,%2};" : "=l"(r) : "f"(x), "f"(y)); return r;
}
__device__ __forceinline__ void upk2(ull v, float& x, float& y) {
    asm("mov.b64 {%0,%1}, %2;" : "=f"(x), "=f"(y) : "l"(v));
}
__device__ __forceinline__ void ffma2(ull& d, ull a, ull b) {
    asm("fma.rn.f32x2 %0, %1, %2, %0;" : "+l"(d) : "l"(a), "l"(b));
}
__device__ __forceinline__ uint to_tf32(float f) {
    uint r; asm("cvt.rna.tf32.f32 %0, %1;" : "=r"(r) : "f"(f)); return r;
}
__device__ __forceinline__ void mma_tf32(float acc[4], const uint a[4], uint b0, uint b1) {
    asm volatile(
        "mma.sync.aligned.m16n8k8.row.col.f32.tf32.tf32.f32 "
        "{%0,%1,%2,%3}, {%4,%5,%6,%7}, {%8,%9}, {%0,%1,%2,%3};"
        : "+f"(acc[0]), "+f"(acc[1]), "+f"(acc[2]), "+f"(acc[3])
        : "r"(a[0]), "r"(a[1]), "r"(a[2]), "r"(a[3]), "r"(b0), "r"(b1));
}

// ================= CSR build ==================================================
__global__ void zero_deg_kernel(int N) {
    int t = blockIdx.x * blockDim.x + threadIdx.x;
    if (t < N) g_deg[t] = 0;
}

__global__ void deg_kernel(const int* __restrict__ ei, int E, int Etot) {
    int i = blockIdx.x * blockDim.x + threadIdx.x;
    if (i >= Etot) return;
    int d = (i < E) ? ei[E + i] : (i - E);
    atomicAdd(&g_deg[d], 1);
}

// single block, 1024 threads, 8 elements/thread per iteration
__global__ void scan_kernel(int N, int Etot) {
    __shared__ int sh[1024];
    __shared__ int s_carry;
    const int tid = threadIdx.x;
    if (tid == 0) s_carry = 0;
    __syncthreads();
    const int CH = 8;
    for (int base = 0; base < N; base += 1024 * CH) {
        int vals[CH];
        int idx0 = base + tid * CH;
        int sum = 0;
        #pragma unroll
        for (int j = 0; j < CH; ++j) {
            int ix = idx0 + j;
            int v = (ix < N) ? g_deg[ix] : 0;
            vals[j] = sum;                 // exclusive within thread
            sum += v;
        }
        sh[tid] = sum;
        __syncthreads();
        for (int off = 1; off < 1024; off <<= 1) {
            int t = (tid >= off) ? sh[tid - off] : 0;
            __syncthreads();
            sh[tid] += t;
            __syncthreads();
        }
        int thread_excl = sh[tid] - sum;
        int carry = s_carry;
        #pragma unroll
        for (int j = 0; j < CH; ++j) {
            int ix = idx0 + j;
            if (ix < N) {
                int rp = carry + thread_excl + vals[j];
                g_rowptr[ix] = rp;
                g_cur[ix]    = rp;
            }
        }
        __syncthreads();
        if (tid == 1023) s_carry = carry + sh[1023];
        __syncthreads();
    }
    if (tid == 0) g_rowptr[N] = Etot;
}

__global__ void scatter_kernel(const int* __restrict__ ei, int E, int Etot) {
    int i = blockIdx.x * blockDim.x + threadIdx.x;
    if (i >= Etot) return;
    int s, d;
    if (i < E) { s = ei[i]; d = ei[E + i]; }
    else       { s = d = i - E; }
    int pos = atomicAdd(&g_cur[d], 1);
    g_csr_src[pos] = s;
    g_csr_eid[pos] = i;
    g_csr_dst[pos] = d;
}

// ---------------- self-loop attr: per-dst gathered mean ----------------------
__global__ void pre_csr_kernel(const float* __restrict__ ea, int E, int N) {
    const int lane = threadIdx.x & 31;
    const int d = blockIdx.x * 8 + (threadIdx.x >> 5);
    if (d >= N) return;
    const int rp0 = g_rowptr[d], rp1 = g_rowptr[d + 1];
    float s = 0.f;
    int cnt = 0;
    for (int e = rp0; e < rp1; ++e) {
        int eid = g_csr_eid[e];
        if (eid < E) {
            s += ea[(size_t)eid * FE + lane];
            ++cnt;
        }
    }
    g_loop[(size_t)d * FE + lane] = s / (float)max(cnt, 1);
}

// ---------------- kernel: node linear transforms (xl | xr) -------------------
template<int IN, bool FROM_OUT>
__global__ void lin_kernel(const float* __restrict__ inp,
                           const float* __restrict__ Wl, const float* __restrict__ bl,
                           const float* __restrict__ Wr, const float* __restrict__ br,
                           const float* __restrict__ prevBias, int N) {
    constexpr int NB = 64;
    __shared__ __align__(16) float xs[NB * (IN + 1)];
    __shared__ __align__(16) float ws[16 * 128];
    const int nb = blockIdx.x * NB;
    const int t = threadIdx.x;

    for (int idx = t; idx < NB * IN; idx += 256) {
        int n = idx / IN, j = idx - n * IN;
        int g = nb + n;
        float v = 0.f;
        if (g < N) {
            if (FROM_OUT) v = fmaxf(g_out[(size_t)g * HID + j] + prevBias[j], 0.f);
            else          v = inp[(size_t)g * IN + j];
        }
        xs[n * (IN + 1) + j] = v;
    }
    __syncthreads();

    const int pg = t & 7;
    const int n0 = (t >> 3) * 2, n1 = n0 + 1;
    ull acc0[8], acc1[8];
    #pragma unroll
    for (int q = 0; q < 8; ++q) { acc0[q] = 0ull; acc1[q] = 0ull; }
    const ull* wsu = reinterpret_cast<const ull*>(ws);

    for (int c = 0; c < IN / 16; ++c) {
        __syncthreads();
        for (int idx = t; idx < 16 * 128; idx += 256) {
            int j = idx >> 7, o = idx & 127;
            int row = c * 16 + j;
            ws[idx] = (o < HID) ? Wl[row * HID + o] : Wr[row * HID + (o - HID)];
        }
        __syncthreads();
        #pragma unroll
        for (int j = 0; j < 16; ++j) {
            float a0 = xs[n0 * (IN + 1) + c * 16 + j];
            float a1 = xs[n1 * (IN + 1) + c * 16 + j];
            ull p0 = pk2(a0, a0), p1 = pk2(a1, a1);
            #pragma unroll
            for (int q = 0; q < 8; ++q) {
                ull wv = wsu[j * 64 + pg + 8 * q];
                ffma2(acc0[q], p0, wv);
                ffma2(acc1[q], p1, wv);
            }
        }
    }

    float2* xl2 = reinterpret_cast<float2*>(g_xl);
    float2* xr2 = reinterpret_cast<float2*>(g_xr);
    #pragma unroll
    for (int which = 0; which < 2; ++which) {
        int n = which ? n1 : n0;
        int g = nb + n;
        if (g >= N) continue;
        ull* acc = which ? acc1 : acc0;
        #pragma unroll
        for (int q = 0; q < 8; ++q) {
            int p = pg + 8 * q;
            int o = 2 * p;
            float vx, vy; upk2(acc[q], vx, vy);
            if (o < HID) {
                xl2[(size_t)g * 32 + p] = make_float2(vx + bl[o], vy + bl[o + 1]);
            } else {
                xr2[(size_t)g * 32 + (p - 32)] = make_float2(vx + br[o - HID], vy + br[o - HID + 1]);
            }
        }
    }
}

// ---------------- edge pass A: tensor-core e-GEMM + logits (CSR order) -------
// Warp handles a tile of 16 CSR slots x HID(64). exp(logit) written to g_exc.
__global__ __launch_bounds__(256) void edgeA_kernel(
        const float* __restrict__ ea,
        const float* __restrict__ We, const float* __restrict__ att,
        int E, int N) {
    __shared__ uint Wes[32 * 68];            // tf32-converted We, padded rows

    const int t = threadIdx.x;
    for (int idx = t; idx < 32 * 64; idx += 256) {
        int row = idx >> 6, col = idx & 63;
        Wes[row * 68 + col] = to_tf32(We[idx]);
    }
    __syncthreads();

    const int lane = t & 31;
    const int w = t >> 5;
    const int g = lane >> 2;                 // row group 0..7
    const int c = lane & 3;                  // col-in-group 0..3
    const int Etot = E + N;
    const int nTiles = (Etot + 15) >> 4;
    const int gw = blockIdx.x * 8 + w;
    const int gws = gridDim.x * 8;

    const float2* xl2 = reinterpret_cast<const float2*>(g_xl);
    const float2* xr2 = reinterpret_cast<const float2*>(g_xr);
    const float2* att2 = reinterpret_cast<const float2*>(att);

    for (int tile = gw; tile < nTiles; tile += gws) {
        const int i0 = tile << 4;
        const int rowA = i0 + g;             // CSR slot for this lane's rows
        const int rowB = i0 + g + 8;

        int sA = 0, dA = 0, sB = 0, dB = 0;
        const float *pA = ea, *pB = ea;
        if (rowA < Etot) {
            int eid = g_csr_eid[rowA];
            sA = g_csr_src[rowA]; dA = g_csr_dst[rowA];
            pA = (eid < E) ? ea + (size_t)eid * FE : g_loop + (size_t)(eid - E) * FE;
        }
        if (rowB < Etot) {
            int eid = g_csr_eid[rowB];
            sB = g_csr_src[rowB]; dB = g_csr_dst[rowB];
            pB = (eid < E) ? ea + (size_t)eid * FE : g_loop + (size_t)(eid - E) * FE;
        }

        // A fragments for all 4 k-steps (m16k8 each)
        uint afr[4][4];
        #pragma unroll
        for (int ks = 0; ks < 4; ++ks) {
            afr[ks][0] = to_tf32(pA[ks * 8 + c]);
            afr[ks][1] = to_tf32(pB[ks * 8 + c]);
            afr[ks][2] = to_tf32(pA[ks * 8 + c + 4]);
            afr[ks][3] = to_tf32(pB[ks * 8 + c + 4]);
        }

        float partA = 0.f, partB = 0.f;
        #pragma unroll
        for (int nt = 0; nt < 8; ++nt) {
            float acc[4] = {0.f, 0.f, 0.f, 0.f};
            #pragma unroll
            for (int ks = 0; ks < 4; ++ks) {
                uint b0 = Wes[(ks * 8 + c)     * 68 + nt * 8 + g];
                uint b1 = Wes[(ks * 8 + c + 4) * 68 + nt * 8 + g];
                mma_tf32(acc, afr[ks], b0, b1);
            }
            float2 xlA = xl2[(size_t)sA * 32 + nt * 4 + c];
            float2 xrA = xr2[(size_t)dA * 32 + nt * 4 + c];
            float2 xlB = xl2[(size_t)sB * 32 + nt * 4 + c];
            float2 xrB = xr2[(size_t)dB * 32 + nt * 4 + c];
            float u0 = acc[0] + xlA.x + xrA.x;
            float u1 = acc[1] + xlA.y + xrA.y;
            float u2 = acc[2] + xlB.x + xrB.x;
            float u3 = acc[3] + xlB.y + xrB.y;
            u0 = fmaxf(u0, 0.f) + 0.2f * fminf(u0, 0.f);
            u1 = fmaxf(u1, 0.f) + 0.2f * fminf(u1, 0.f);
            u2 = fmaxf(u2, 0.f) + 0.2f * fminf(u2, 0.f);
            u3 = fmaxf(u3, 0.f) + 0.2f * fminf(u3, 0.f);
            float2 av = att2[nt * 4 + c];
            partA = fmaf(u0, av.x, fmaf(u1, av.y, partA));
            partB = fmaf(u2, av.x, fmaf(u3, av.y, partB));
        }
        partA += __shfl_xor_sync(0xffffffffu, partA, 1);
        partA += __shfl_xor_sync(0xffffffffu, partA, 2);
        partB += __shfl_xor_sync(0xffffffffu, partB, 1);
        partB += __shfl_xor_sync(0xffffffffu, partB, 2);
        if (c == 0) {
            if (rowA < Etot) g_exc[rowA] = __expf(partA);
            if (rowB < Etot) g_exc[rowB] = __expf(partB);
        }
    }
}

// ---------------- edge pass B: per-dst softmax-normalize + aggregate ---------
__global__ __launch_bounds__(256) void edgeB_kernel(int N) {
    const int lane = threadIdx.x & 31;
    const int d = blockIdx.x * 8 + (threadIdx.x >> 5);
    if (d >= N) return;
    const int rp0 = g_rowptr[d], rp1 = g_rowptr[d + 1];

    // denominator: sequential reads of g_exc over the segment
    float den = 0.f;
    for (int e = rp0 + lane; e < rp1; e += 32) den += g_exc[e];
    #pragma unroll
    for (int off = 16; off > 0; off >>= 1)
        den += __shfl_xor_sync(0xffffffffu, den, off);
    const float inv = 1.f / den;

    const float2* xl2 = reinterpret_cast<const float2*>(g_xl);
    float ax = 0.f, ay = 0.f;
    if (rp0 < rp1) {
        int src = g_csr_src[rp0];
        float wgt = g_exc[rp0];
        for (int e = rp0 + 1; e <= rp1; ++e) {
            int nsrc = 0; float nw = 0.f;
            if (e < rp1) { nsrc = g_csr_src[e]; nw = g_exc[e]; }
            float2 xv = xl2[(size_t)src * 32 + lane];
            ax = fmaf(wgt, xv.x, ax);
            ay = fmaf(wgt, xv.y, ay);
            src = nsrc; wgt = nw;
        }
    }
    float2* out2 = reinterpret_cast<float2*>(g_out);
    out2[(size_t)d * 32 + lane] = make_float2(ax * inv, ay * inv);
}

// ---------------- kernel: final MLP at node_idx ------------------------------
__global__ void fin_kernel(const int* __restrict__ idx, const float* __restrict__ bias2,
                           const float* __restrict__ y,
                           const float* __restrict__ W0, const float* __restrict__ b0,
                           const float* __restrict__ W1, const float* __restrict__ b1,
                           const float* __restrict__ W2, const float* __restrict__ b2,
                           float* __restrict__ dout, int M, int rf) {
    __shared__ float sh[4][64];
    __shared__ float sz[4][32];
    const int w = threadIdx.x >> 5, lane = threadIdx.x & 31;
    const int m = blockIdx.x * 4 + w;
    if (m >= M) return;
    const int v = idx[m];

    float h0 = fmaxf(g_out[(size_t)v * HID + lane]      + bias2[lane],      0.f);
    float h1 = fmaxf(g_out[(size_t)v * HID + 32 + lane] + bias2[32 + lane], 0.f);
    sh[w][lane] = h0; sh[w][32 + lane] = h1;
    __syncwarp();

    int k = v / rf;
    float y0 = y[2 * k], y1 = y[2 * k + 1];
    float q0 = fmaxf(y0 * W0[0] + y1 * W0[2] + b0[0], 0.f);
    float q1 = fmaxf(y0 * W0[1] + y1 * W0[3] + b0[1], 0.f);

    float z = b1[lane];
    #pragma unroll
    for (int j = 0; j < 64; ++j) z += sh[w][j] * W1[j * 32 + lane];
    z += q0 * W1[64 * 32 + lane] + q1 * W1[65 * 32 + lane];
    z = fmaxf(z, 0.f);
    sz[w][lane] = z;
    __syncwarp();

    float o = b2[lane];
    #pragma unroll
    for (int j = 0; j < 32; ++j) o += sz[w][j] * W2[j * 32 + lane];
    dout[m * 32 + lane] = o;
}

// ---------------- launch ------------------------------------------------------
extern "C" void kernel_launch(void* const* d_in, const int* in_sizes, int n_in,
                              void* d_out, int out_size) {
    const float* x    = (const float*)d_in[0];
    const float* ea   = (const float*)d_in[1];
    const float* y    = (const float*)d_in[2];
    const float* Wl1  = (const float*)d_in[3];
    const float* bl1  = (const float*)d_in[4];
    const float* Wr1  = (const float*)d_in[5];
    const float* br1  = (const float*)d_in[6];
    const float* We1  = (const float*)d_in[7];
    const float* att1 = (const float*)d_in[8];
    const float* bias1= (const float*)d_in[9];
    const float* Wl2  = (const float*)d_in[10];
    const float* bl2  = (const float*)d_in[11];
    const float* Wr2  = (const float*)d_in[12];
    const float* br2  = (const float*)d_in[13];
    const float* We2  = (const float*)d_in[14];
    const float* att2 = (const float*)d_in[15];
    const float* bias2= (const float*)d_in[16];
    const float* W0   = (const float*)d_in[17];
    const float* b0   = (const float*)d_in[18];
    const float* W1   = (const float*)d_in[19];
    const float* b1   = (const float*)d_in[20];
    const float* W2   = (const float*)d_in[21];
    const float* b2   = (const float*)d_in[22];
    const int*   ei   = (const int*)  d_in[23];
    const int*   nidx = (const int*)  d_in[24];

    const int N    = in_sizes[0] / FN;
    const int E    = in_sizes[23] / 2;
    const int Etot = E + N;
    const int M    = in_sizes[24];
    const int NG   = in_sizes[2] / 2;
    const int rf   = N / NG;

    const int EBLK = (Etot + 255) / 256;
    const int NWRP = (N + 7) / 8;        // warp-per-node kernels

    // ---- CSR build (group edges by destination) ----
    zero_deg_kernel<<<(N + 255) / 256, 256>>>(N);
    deg_kernel     <<<EBLK, 256>>>(ei, E, Etot);
    scan_kernel    <<<1, 1024>>>(N, Etot);
    scatter_kernel <<<EBLK, 256>>>(ei, E, Etot);
    pre_csr_kernel <<<NWRP, 256>>>(ea, E, N);

    // ---- layer 1 ----
    lin_kernel<FN, false><<<(N + 63) / 64, 256>>>(x, Wl1, bl1, Wr1, br1, nullptr, N);
    edgeA_kernel<<<2048, 256>>>(ea, We1, att1, E, N);
    edgeB_kernel<<<NWRP, 256>>>(N);

    // ---- layer 2 ----
    lin_kernel<HID, true><<<(N + 63) / 64, 256>>>(x, Wl2, bl2, Wr2, br2, bias1, N);
    edgeA_kernel<<<2048, 256>>>(ea, We2, att2, E, N);
    edgeB_kernel<<<NWRP, 256>>>(N);

    // ---- final MLP at node_idx ----
    fin_kernel<<<(M + 3) / 4, 128>>>(nidx, bias2, y, W0, b0, W1, b1, W2, b2,
                                     (float*)d_out, M, rf);
}

// round 4
// speedup vs baseline: 2.5610x; 1.2695x over previous
#include <cuda_runtime.h>
#include <cstddef>

typedef unsigned long long ull;
typedef unsigned int uint;

// ---------------- problem constants (shapes fixed by the dataset) -----------
#define MAXN 100000
#define MAXE 1600000
#define MAXET (MAXE + MAXN)
#define FN   128     // node feature dim (layer1 input)
#define FE   32      // edge feature dim
#define HID  64

// ---------------- device scratch (static: no allocation allowed) ------------
__device__ float g_loop[MAXN * FE];        // self-loop edge attr (mean of incoming)
__device__ float g_xl  [MAXN * HID];       // source-side transform
__device__ float g_xr  [MAXN * HID];       // target-side transform
__device__ float g_exc [MAXET];            // exp(logit) in CSR slot order
__device__ float g_out [MAXN * HID];       // layer output
__device__ int   g_deg [MAXN];
__device__ int   g_rowptr[MAXN + 1];
__device__ int   g_cur [MAXN];
__device__ int   g_bsum[128];
__device__ int2  g_csr_se [MAXET];         // (src, eid) packed
__device__ int   g_csr_dst[MAXET];

// ---------------- small helpers ---------------------------------------------
__device__ __forceinline__ uint to_tf32(float f) {
    uint r; asm("cvt.rna.tf32.f32 %0, %1;" : "=r"(r) : "f"(f)); return r;
}
__device__ __forceinline__ void tf32_split(float v, uint& hb, uint& lb) {
    asm("cvt.rna.tf32.f32 %0, %1;" : "=r"(hb) : "f"(v));
    float hf = __uint_as_float(hb);
    asm("cvt.rna.tf32.f32 %0, %1;" : "=r"(lb) : "f"(v - hf));
}
__device__ __forceinline__ void mma_tf32(float acc[4], const uint a[4], uint b0, uint b1) {
    asm volatile(
        "mma.sync.aligned.m16n8k8.row.col.f32.tf32.tf32.f32 "
        "{%0,%1,%2,%3}, {%4,%5,%6,%7}, {%8,%9}, {%0,%1,%2,%3};"
        : "+f"(acc[0]), "+f"(acc[1]), "+f"(acc[2]), "+f"(acc[3])
        : "r"(a[0]), "r"(a[1]), "r"(a[2]), "r"(a[3]), "r"(b0), "r"(b1));
}

// ================= CSR build ==================================================
__global__ void zero_deg_kernel(int N) {
    int t = blockIdx.x * blockDim.x + threadIdx.x;
    if (t < N) g_deg[t] = 0;
}

__global__ void deg_kernel(const int* __restrict__ ei, int E, int Etot) {
    int i = blockIdx.x * blockDim.x + threadIdx.x;
    if (i >= Etot) return;
    int d = (i < E) ? ei[E + i] : (i - E);
    atomicAdd(&g_deg[d], 1);
}

// grid scan stage A: per-block exclusive scan + block sums
__global__ __launch_bounds__(1024) void scanA_kernel(int N) {
    __shared__ int wsum[32];
    const int i = blockIdx.x * 1024 + threadIdx.x;
    const int lane = threadIdx.x & 31, wid = threadIdx.x >> 5;
    int v = (i < N) ? g_deg[i] : 0;
    int s = v;
    #pragma unroll
    for (int off = 1; off < 32; off <<= 1) {
        int t = __shfl_up_sync(0xffffffffu, s, off);
        if (lane >= off) s += t;
    }
    if (lane == 31) wsum[wid] = s;
    __syncthreads();
    if (wid == 0) {
        int ws = wsum[lane];
        #pragma unroll
        for (int off = 1; off < 32; off <<= 1) {
            int t = __shfl_up_sync(0xffffffffu, ws, off);
            if (lane >= off) ws += t;
        }
        wsum[lane] = ws;
    }
    __syncthreads();
    int excl = s - v + (wid ? wsum[wid - 1] : 0);
    if (i < N) g_rowptr[i] = excl;
    if (threadIdx.x == 1023) g_bsum[blockIdx.x] = excl + v;
}

// stage B: exclusive scan of block sums (single block, nb <= 128)
__global__ void scanB_kernel(int nb) {
    __shared__ int sh[128];
    const int t = threadIdx.x;
    int v = (t < nb) ? g_bsum[t] : 0;
    sh[t] = v;
    __syncthreads();
    for (int off = 1; off < 128; off <<= 1) {
        int x = (t >= off) ? sh[t - off] : 0;
        __syncthreads();
        sh[t] += x;
        __syncthreads();
    }
    g_bsum[t] = sh[t] - v;
}

// stage C: add block offsets, init cursors
__global__ __launch_bounds__(1024) void scanC_kernel(int N, int Etot) {
    int i = blockIdx.x * 1024 + threadIdx.x;
    if (i < N) {
        int rp = g_rowptr[i] + g_bsum[blockIdx.x];
        g_rowptr[i] = rp;
        g_cur[i]    = rp;
    }
    if (i == 0) g_rowptr[N] = Etot;
}

__global__ void scatter_kernel(const int* __restrict__ ei, int E, int Etot) {
    int i = blockIdx.x * blockDim.x + threadIdx.x;
    if (i >= Etot) return;
    int s, d;
    if (i < E) { s = ei[i]; d = ei[E + i]; }
    else       { s = d = i - E; }
    int pos = atomicAdd(&g_cur[d], 1);
    g_csr_se[pos]  = make_int2(s, i);
    g_csr_dst[pos] = d;
}

// ---------------- self-loop attr: per-dst gathered mean ----------------------
__global__ void pre_csr_kernel(const float* __restrict__ ea, int E, int N) {
    const int lane = threadIdx.x & 31;
    const int d = blockIdx.x * 8 + (threadIdx.x >> 5);
    if (d >= N) return;
    const int rp0 = g_rowptr[d], rp1 = g_rowptr[d + 1];
    float s = 0.f;
    int cnt = 0;
    for (int e = rp0; e < rp1; ++e) {
        int eid = g_csr_se[e].y;
        if (eid < E) {
            s += ea[(size_t)eid * FE + lane];
            ++cnt;
        }
    }
    g_loop[(size_t)d * FE + lane] = s / (float)max(cnt, 1);
}

// ---------------- node linear transforms via 3xTF32 tensor MMA ---------------
// Block: 256 threads (8 warps), 64 nodes, 128 outputs (Wl cols | Wr cols).
// Warp w: m-tile = w&3 (16 nodes), half = w>>2 (0 -> xl, 1 -> xr).
template<int IN, bool FROM_OUT>
__global__ __launch_bounds__(256) void lin_mma_kernel(
        const float* __restrict__ inp,
        const float* __restrict__ Wl, const float* __restrict__ bl,
        const float* __restrict__ Wr, const float* __restrict__ br,
        const float* __restrict__ prevBias, int N) {
    constexpr int KC = 16;
    __shared__ uint XsH[64][20], XsL[64][20];
    __shared__ uint WsH[KC][132], WsL[KC][132];

    const int t = threadIdx.x;
    const int nb = blockIdx.x * 64;
    const int lane = t & 31;
    const int w = t >> 5;
    const int mt = w & 3;
    const int half = w >> 2;
    const int g = lane >> 2, c = lane & 3;

    float acc[8][4];
    #pragma unroll
    for (int nt = 0; nt < 8; ++nt) {
        acc[nt][0] = acc[nt][1] = acc[nt][2] = acc[nt][3] = 0.f;
    }

    for (int kc = 0; kc < IN; kc += KC) {
        __syncthreads();
        // stage X chunk (64 x KC) as tf32 hi/lo
        for (int idx = t; idx < 64 * KC; idx += 256) {
            int row = idx / KC, col = idx - row * KC;
            int node = nb + row;
            float v = 0.f;
            if (node < N) {
                int j = kc + col;
                if (FROM_OUT) v = fmaxf(g_out[(size_t)node * HID + j] + prevBias[j], 0.f);
                else          v = inp[(size_t)node * IN + j];
            }
            uint hb, lb; tf32_split(v, hb, lb);
            XsH[row][col] = hb; XsL[row][col] = lb;
        }
        // stage W chunk (KC x 128): cols 0..63 = Wl, 64..127 = Wr
        for (int idx = t; idx < KC * 128; idx += 256) {
            int row = idx >> 7, col = idx & 127;
            int k = kc + row;
            float v = (col < HID) ? Wl[k * HID + col] : Wr[k * HID + (col - HID)];
            uint hb, lb; tf32_split(v, hb, lb);
            WsH[row][col] = hb; WsL[row][col] = lb;
        }
        __syncthreads();
        #pragma unroll
        for (int kk = 0; kk < KC; kk += 8) {
            uint aH[4], aL[4];
            aH[0] = XsH[mt * 16 + g    ][kk + c];
            aH[1] = XsH[mt * 16 + g + 8][kk + c];
            aH[2] = XsH[mt * 16 + g    ][kk + c + 4];
            aH[3] = XsH[mt * 16 + g + 8][kk + c + 4];
            aL[0] = XsL[mt * 16 + g    ][kk + c];
            aL[1] = XsL[mt * 16 + g + 8][kk + c];
            aL[2] = XsL[mt * 16 + g    ][kk + c + 4];
            aL[3] = XsL[mt * 16 + g + 8][kk + c + 4];
            #pragma unroll
            for (int nt = 0; nt < 8; ++nt) {
                int col = half * 64 + nt * 8 + g;
                uint bH0 = WsH[kk + c    ][col];
                uint bH1 = WsH[kk + c + 4][col];
                uint bL0 = WsL[kk + c    ][col];
                uint bL1 = WsL[kk + c + 4][col];
                mma_tf32(acc[nt], aH, bH0, bH1);   // hi*hi
                mma_tf32(acc[nt], aL, bH0, bH1);   // lo*hi
                mma_tf32(acc[nt], aH, bL0, bL1);   // hi*lo
            }
        }
    }

    // epilogue: add bias, write float2
    const float* bias = half ? br : bl;
    float2* dst2 = reinterpret_cast<float2*>(half ? g_xr : g_xl);
    const int m0 = nb + mt * 16 + g;
    const int m1 = m0 + 8;
    #pragma unroll
    for (int nt = 0; nt < 8; ++nt) {
        int colL = nt * 8 + 2 * c;
        float bx = bias[colL], by = bias[colL + 1];
        if (m0 < N) dst2[(size_t)m0 * 32 + nt * 4 + c] = make_float2(acc[nt][0] + bx, acc[nt][1] + by);
        if (m1 < N) dst2[(size_t)m1 * 32 + nt * 4 + c] = make_float2(acc[nt][2] + bx, acc[nt][3] + by);
    }
}

// ---------------- edge pass A: tensor-core e-GEMM + logits (CSR order) -------
__global__ __launch_bounds__(256) void edgeA_kernel(
        const float* __restrict__ ea,
        const float* __restrict__ We, const float* __restrict__ att,
        int E, int N) {
    __shared__ uint Wes[32 * 68];            // tf32-converted We, padded rows

    const int t = threadIdx.x;
    for (int idx = t; idx < 32 * 64; idx += 256) {
        int row = idx >> 6, col = idx & 63;
        Wes[row * 68 + col] = to_tf32(We[idx]);
    }
    __syncthreads();

    const int lane = t & 31;
    const int w = t >> 5;
    const int g = lane >> 2;                 // row group 0..7
    const int c = lane & 3;                  // col-in-group 0..3
    const int Etot = E + N;
    const int nTiles = (Etot + 15) >> 4;
    const int gw = blockIdx.x * 8 + w;
    const int gws = gridDim.x * 8;

    const float2* xl2 = reinterpret_cast<const float2*>(g_xl);
    const float2* xr2 = reinterpret_cast<const float2*>(g_xr);
    const float2* att2 = reinterpret_cast<const float2*>(att);

    for (int tile = gw; tile < nTiles; tile += gws) {
        const int i0 = tile << 4;
        const int rowA = i0 + g;
        const int rowB = i0 + g + 8;

        int sA = 0, dA = 0, sB = 0, dB = 0;
        const float *pA = ea, *pB = ea;
        if (rowA < Etot) {
            int2 se = g_csr_se[rowA];
            sA = se.x; dA = g_csr_dst[rowA];
            pA = (se.y < E) ? ea + (size_t)se.y * FE : g_loop + (size_t)(se.y - E) * FE;
        }
        if (rowB < Etot) {
            int2 se = g_csr_se[rowB];
            sB = se.x; dB = g_csr_dst[rowB];
            pB = (se.y < E) ? ea + (size_t)se.y * FE : g_loop + (size_t)(se.y - E) * FE;
        }

        uint afr[4][4];
        #pragma unroll
        for (int ks = 0; ks < 4; ++ks) {
            afr[ks][0] = to_tf32(pA[ks * 8 + c]);
            afr[ks][1] = to_tf32(pB[ks * 8 + c]);
            afr[ks][2] = to_tf32(pA[ks * 8 + c + 4]);
            afr[ks][3] = to_tf32(pB[ks * 8 + c + 4]);
        }

        float partA = 0.f, partB = 0.f;
        #pragma unroll
        for (int nt = 0; nt < 8; ++nt) {
            float acc[4] = {0.f, 0.f, 0.f, 0.f};
            #pragma unroll
            for (int ks = 0; ks < 4; ++ks) {
                uint b0 = Wes[(ks * 8 + c)     * 68 + nt * 8 + g];
                uint b1 = Wes[(ks * 8 + c + 4) * 68 + nt * 8 + g];
                mma_tf32(acc, afr[ks], b0, b1);
            }
            float2 xlA = xl2[(size_t)sA * 32 + nt * 4 + c];
            float2 xrA = xr2[(size_t)dA * 32 + nt * 4 + c];
            float2 xlB = xl2[(size_t)sB * 32 + nt * 4 + c];
            float2 xrB = xr2[(size_t)dB * 32 + nt * 4 + c];
            float u0 = acc[0] + xlA.x + xrA.x;
            float u1 = acc[1] + xlA.y + xrA.y;
            float u2 = acc[2] + xlB.x + xrB.x;
            float u3 = acc[3] + xlB.y + xrB.y;
            u0 = fmaxf(u0, 0.f) + 0.2f * fminf(u0, 0.f);
            u1 = fmaxf(u1, 0.f) + 0.2f * fminf(u1, 0.f);
            u2 = fmaxf(u2, 0.f) + 0.2f * fminf(u2, 0.f);
            u3 = fmaxf(u3, 0.f) + 0.2f * fminf(u3, 0.f);
            float2 av = att2[nt * 4 + c];
            partA = fmaf(u0, av.x, fmaf(u1, av.y, partA));
            partB = fmaf(u2, av.x, fmaf(u3, av.y, partB));
        }
        partA += __shfl_xor_sync(0xffffffffu, partA, 1);
        partA += __shfl_xor_sync(0xffffffffu, partA, 2);
        partB += __shfl_xor_sync(0xffffffffu, partB, 1);
        partB += __shfl_xor_sync(0xffffffffu, partB, 2);
        if (c == 0) {
            if (rowA < Etot) g_exc[rowA] = __expf(partA);
            if (rowB < Etot) g_exc[rowB] = __expf(partB);
        }
    }
}

// ---------------- edge pass B: per-dst softmax-normalize + aggregate ---------
__global__ __launch_bounds__(256) void edgeB_kernel(int N) {
    const int lane = threadIdx.x & 31;
    const int d = blockIdx.x * 8 + (threadIdx.x >> 5);
    if (d >= N) return;
    const int rp0 = g_rowptr[d], rp1 = g_rowptr[d + 1];

    float den = 0.f;
    for (int e = rp0 + lane; e < rp1; e += 32) den += g_exc[e];
    #pragma unroll
    for (int off = 16; off > 0; off >>= 1)
        den += __shfl_xor_sync(0xffffffffu, den, off);
    const float inv = 1.f / den;

    const float2* xl2 = reinterpret_cast<const float2*>(g_xl);
    float ax = 0.f, ay = 0.f;
    if (rp0 < rp1) {
        int src = g_csr_se[rp0].x;
        float wgt = g_exc[rp0];
        for (int e = rp0 + 1; e <= rp1; ++e) {
            int nsrc = 0; float nw = 0.f;
            if (e < rp1) { nsrc = g_csr_se[e].x; nw = g_exc[e]; }
            float2 xv = xl2[(size_t)src * 32 + lane];
            ax = fmaf(wgt, xv.x, ax);
            ay = fmaf(wgt, xv.y, ay);
            src = nsrc; wgt = nw;
        }
    }
    float2* out2 = reinterpret_cast<float2*>(g_out);
    out2[(size_t)d * 32 + lane] = make_float2(ax * inv, ay * inv);
}

// ---------------- kernel: final MLP at node_idx ------------------------------
__global__ void fin_kernel(const int* __restrict__ idx, const float* __restrict__ bias2,
                           const float* __restrict__ y,
                           const float* __restrict__ W0, const float* __restrict__ b0,
                           const float* __restrict__ W1, const float* __restrict__ b1,
                           const float* __restrict__ W2, const float* __restrict__ b2,
                           float* __restrict__ dout, int M, int rf) {
    __shared__ float sh[4][64];
    __shared__ float sz[4][32];
    const int w = threadIdx.x >> 5, lane = threadIdx.x & 31;
    const int m = blockIdx.x * 4 + w;
    if (m >= M) return;
    const int v = idx[m];

    float h0 = fmaxf(g_out[(size_t)v * HID + lane]      + bias2[lane],      0.f);
    float h1 = fmaxf(g_out[(size_t)v * HID + 32 + lane] + bias2[32 + lane], 0.f);
    sh[w][lane] = h0; sh[w][32 + lane] = h1;
    __syncwarp();

    int k = v / rf;
    float y0 = y[2 * k], y1 = y[2 * k + 1];
    float q0 = fmaxf(y0 * W0[0] + y1 * W0[2] + b0[0], 0.f);
    float q1 = fmaxf(y0 * W0[1] + y1 * W0[3] + b0[1], 0.f);

    float z = b1[lane];
    #pragma unroll
    for (int j = 0; j < 64; ++j) z += sh[w][j] * W1[j * 32 + lane];
    z += q0 * W1[64 * 32 + lane] + q1 * W1[65 * 32 + lane];
    z = fmaxf(z, 0.f);
    sz[w][lane] = z;
    __syncwarp();

    float o = b2[lane];
    #pragma unroll
    for (int j = 0; j < 32; ++j) o += sz[w][j] * W2[j * 32 + lane];
    dout[m * 32 + lane] = o;
}

// ---------------- launch ------------------------------------------------------
extern "C" void kernel_launch(void* const* d_in, const int* in_sizes, int n_in,
                              void* d_out, int out_size) {
    const float* x    = (const float*)d_in[0];
    const float* ea   = (const float*)d_in[1];
    const float* y    = (const float*)d_in[2];
    const float* Wl1  = (const float*)d_in[3];
    const float* bl1  = (const float*)d_in[4];
    const float* Wr1  = (const float*)d_in[5];
    const float* br1  = (const float*)d_in[6];
    const float* We1  = (const float*)d_in[7];
    const float* att1 = (const float*)d_in[8];
    const float* bias1= (const float*)d_in[9];
    const float* Wl2  = (const float*)d_in[10];
    const float* bl2  = (const float*)d_in[11];
    const float* Wr2  = (const float*)d_in[12];
    const float* br2  = (const float*)d_in[13];
    const float* We2  = (const float*)d_in[14];
    const float* att2 = (const float*)d_in[15];
    const float* bias2= (const float*)d_in[16];
    const float* W0   = (const float*)d_in[17];
    const float* b0   = (const float*)d_in[18];
    const float* W1   = (const float*)d_in[19];
    const float* b1   = (const float*)d_in[20];
    const float* W2   = (const float*)d_in[21];
    const float* b2   = (const float*)d_in[22];
    const int*   ei   = (const int*)  d_in[23];
    const int*   nidx = (const int*)  d_in[24];

    const int N    = in_sizes[0] / FN;
    const int E    = in_sizes[23] / 2;
    const int Etot = E + N;
    const int M    = in_sizes[24];
    const int NG   = in_sizes[2] / 2;
    const int rf   = N / NG;

    const int EBLK = (Etot + 255) / 256;
    const int NWRP = (N + 7) / 8;        // warp-per-node kernels
    const int NB1K = (N + 1023) / 1024;  // 1024-thread node kernels

    // ---- CSR build (group edges by destination) ----
    zero_deg_kernel<<<(N + 255) / 256, 256>>>(N);
    deg_kernel     <<<EBLK, 256>>>(ei, E, Etot);
    scanA_kernel   <<<NB1K, 1024>>>(N);
    scanB_kernel   <<<1, 128>>>(NB1K);
    scanC_kernel   <<<NB1K, 1024>>>(N, Etot);
    scatter_kernel <<<EBLK, 256>>>(ei, E, Etot);
    pre_csr_kernel <<<NWRP, 256>>>(ea, E, N);

    // ---- layer 1 ----
    lin_mma_kernel<FN, false><<<(N + 63) / 64, 256>>>(x, Wl1, bl1, Wr1, br1, nullptr, N);
    edgeA_kernel<<<2048, 256>>>(ea, We1, att1, E, N);
    edgeB_kernel<<<NWRP, 256>>>(N);

    // ---- layer 2 ----
    lin_mma_kernel<HID, true><<<(N + 63) / 64, 256>>>(x, Wl2, bl2, Wr2, br2, bias1, N);
    edgeA_kernel<<<2048, 256>>>(ea, We2, att2, E, N);
    edgeB_kernel<<<NWRP, 256>>>(N);

    // ---- final MLP at node_idx ----
    fin_kernel<<<(M + 3) / 4, 128>>>(nidx, bias2, y, W0, b0, W1, b1, W2, b2,
                                     (float*)d_out, M, rf);
}